// round 1
// baseline (speedup 1.0000x reference)
#include <cuda_runtime.h>
#include <math.h>

// ---------------------------------------------------------------------------
// Problem shapes (fixed by the dataset):
//   B=32, Lp=1024, Lq=1024, Lv=512, D=512
//   pre: [B,Lp,D]  q: [B,Lq,D]  v: [B,Lv,D]   all fp32 row-major
// Outputs (concatenated in reference return order):
//   weightedContext [B,Lq,D], energy [B,Lq,D], precompute [B,Lp,D]
// ---------------------------------------------------------------------------

namespace {

constexpr int BM = 128, BN = 128, BK = 16, TM = 8, TN = 8;

// Scratch (device globals — allocation-guard-safe).
__device__ float g_S1[32u * 1024u * 1024u];  // scores pre·q^T  (134 MB)
__device__ float g_S2[32u * 1024u * 512u];   // scores q·v^T    ( 67 MB)

// ---------------------------------------------------------------------------
// Batched SGEMM: C[b] = alpha * A[b] (.) B[b]
//   TRANS_B = true :  C[M,N] = A[M,K] * B[N,K]^T   (both row-major)
//   TRANS_B = false:  C[M,N] = A[M,K] * B[K,N]
// Batch strides: A: M*K, B: N*K, C: M*N (all per-batch contiguous here).
// Requires M%128==0, N%128==0 (for NT path N%128; NN path N%128 too since
// BN=128), K%16==0 — all satisfied by the fixed shapes.
// ---------------------------------------------------------------------------
template <bool TRANS_B>
__global__ __launch_bounds__(256, 2)
void sgemm_kernel(const float* __restrict__ A, const float* __restrict__ B,
                  float* __restrict__ C, int M, int N, int K, float alpha)
{
    const int bz = blockIdx.z;
    A += (size_t)bz * M * K;
    B += (size_t)bz * N * K;
    C += (size_t)bz * M * N;

    __shared__ float As[BK][BM];
    __shared__ float Bs[BK][BN];

    const int tid = threadIdx.x;          // 0..255
    const int tx  = tid & 15;             // 16 col-threads
    const int ty  = tid >> 4;             // 16 row-threads

    const int rowA0 = blockIdx.y * BM;
    const int colB0 = blockIdx.x * BN;

    float acc[TM][TN];
#pragma unroll
    for (int i = 0; i < TM; i++)
#pragma unroll
        for (int j = 0; j < TN; j++) acc[i][j] = 0.0f;

    for (int kt = 0; kt < K; kt += BK) {
        // ---- load A tile (BM x BK), store transposed As[k][m] ----
#pragma unroll
        for (int it = 0; it < 2; it++) {
            const int s = tid + it * 256;       // 0..511 float4 slots
            const int r = s >> 2;               // 0..127 (row in tile)
            const int c = (s & 3) << 2;         // 0,4,8,12 (k offset)
            const float4 va = *reinterpret_cast<const float4*>(
                A + (size_t)(rowA0 + r) * K + (kt + c));
            As[c + 0][r] = va.x;
            As[c + 1][r] = va.y;
            As[c + 2][r] = va.z;
            As[c + 3][r] = va.w;
        }
        // ---- load B tile, store Bs[k][n] ----
        if (TRANS_B) {
#pragma unroll
            for (int it = 0; it < 2; it++) {
                const int s = tid + it * 256;
                const int r = s >> 2;           // 0..127 (n in tile)
                const int c = (s & 3) << 2;     // k offset
                const float4 vb = *reinterpret_cast<const float4*>(
                    B + (size_t)(colB0 + r) * K + (kt + c));
                Bs[c + 0][r] = vb.x;
                Bs[c + 1][r] = vb.y;
                Bs[c + 2][r] = vb.z;
                Bs[c + 3][r] = vb.w;
            }
        } else {
#pragma unroll
            for (int it = 0; it < 2; it++) {
                const int s = tid + it * 256;
                const int r = s >> 5;           // 0..15 (k in tile)
                const int c = (s & 31) << 2;    // 0..124 (n offset)
                const float4 vb = *reinterpret_cast<const float4*>(
                    B + (size_t)(kt + r) * N + (colB0 + c));
                *reinterpret_cast<float4*>(&Bs[r][c]) = vb;
            }
        }
        __syncthreads();

        // ---- compute 8x8 per thread ----
#pragma unroll
        for (int kk = 0; kk < BK; kk++) {
            float a[TM], b[TN];
#pragma unroll
            for (int i = 0; i < TM; i += 4)
                *reinterpret_cast<float4*>(&a[i]) =
                    *reinterpret_cast<const float4*>(&As[kk][ty * TM + i]);
#pragma unroll
            for (int j = 0; j < TN; j += 4)
                *reinterpret_cast<float4*>(&b[j]) =
                    *reinterpret_cast<const float4*>(&Bs[kk][tx * TN + j]);
#pragma unroll
            for (int i = 0; i < TM; i++)
#pragma unroll
                for (int j = 0; j < TN; j++)
                    acc[i][j] = fmaf(a[i], b[j], acc[i][j]);
        }
        __syncthreads();
    }

    const int rowC = rowA0 + ty * TM;
    const int colC = colB0 + tx * TN;
#pragma unroll
    for (int i = 0; i < TM; i++) {
#pragma unroll
        for (int j = 0; j < TN; j += 4) {
            float4 o;
            o.x = acc[i][j + 0] * alpha;
            o.y = acc[i][j + 1] * alpha;
            o.z = acc[i][j + 2] * alpha;
            o.w = acc[i][j + 3] * alpha;
            *reinterpret_cast<float4*>(C + (size_t)(rowC + i) * N + (colC + j)) = o;
        }
    }
}

// ---------------------------------------------------------------------------
// Row softmax (in place). One 256-thread block per row. ELEMS = W/256.
// ---------------------------------------------------------------------------
template <int ELEMS>
__global__ __launch_bounds__(256)
void softmax_rows_kernel(float* __restrict__ S, int W)
{
    float* p = S + (size_t)blockIdx.x * W;
    const int tid = threadIdx.x;

    float vals[ELEMS];
    float m = -3.4e38f;
#pragma unroll
    for (int i = 0; i < ELEMS; i++) {
        vals[i] = p[tid + (i << 8)];
        m = fmaxf(m, vals[i]);
    }

    __shared__ float red[8];
    __shared__ float bc;

    // block max
#pragma unroll
    for (int o = 16; o > 0; o >>= 1)
        m = fmaxf(m, __shfl_xor_sync(0xffffffffu, m, o));
    if ((tid & 31) == 0) red[tid >> 5] = m;
    __syncthreads();
    if (tid == 0) {
        float t = red[0];
#pragma unroll
        for (int i = 1; i < 8; i++) t = fmaxf(t, red[i]);
        bc = t;
    }
    __syncthreads();
    m = bc;

    float s = 0.0f;
#pragma unroll
    for (int i = 0; i < ELEMS; i++) {
        vals[i] = expf(vals[i] - m);
        s += vals[i];
    }
    __syncthreads();  // red[] reuse barrier

    // block sum
#pragma unroll
    for (int o = 16; o > 0; o >>= 1)
        s += __shfl_xor_sync(0xffffffffu, s, o);
    if ((tid & 31) == 0) red[tid >> 5] = s;
    __syncthreads();
    if (tid == 0) {
        float t = red[0];
#pragma unroll
        for (int i = 1; i < 8; i++) t += red[i];
        bc = 1.0f / t;
    }
    __syncthreads();
    const float inv = bc;

#pragma unroll
    for (int i = 0; i < ELEMS; i++)
        p[tid + (i << 8)] = vals[i] * inv;
}

}  // namespace

// ---------------------------------------------------------------------------
extern "C" void kernel_launch(void* const* d_in, const int* in_sizes, int n_in,
                              void* d_out, int out_size)
{
    const float* pre = (const float*)d_in[0];  // [32,1024,512]
    const float* q   = (const float*)d_in[1];  // [32,1024,512]
    const float* v   = (const float*)d_in[2];  // [32, 512,512]
    float* out = (float*)d_out;

    const int B = 32, Lp = 1024, Lq = 1024, Lv = 512, D = 512;
    const float scale = 0.04419417382415922f;  // 1/sqrt(512)

    float* wc     = out;                                  // [B,Lq,D]
    float* energy = out + (size_t)B * Lq * D;             // [B,Lq,D]
    float* prec   = out + 2 * (size_t)B * Lq * D;         // [B,Lp,D]

    float *S1, *S2;
    cudaGetSymbolAddress((void**)&S1, g_S1);
    cudaGetSymbolAddress((void**)&S2, g_S2);

    const dim3 blk(256);

    // ---- precompute = softmax(pre . q^T * scale) . q ----
    sgemm_kernel<true ><<<dim3(Lq / BN, Lp / BM, B), blk>>>(pre, q, S1, Lp, Lq, D, scale);
    softmax_rows_kernel<4><<<B * Lp, blk>>>(S1, Lq);
    sgemm_kernel<false><<<dim3(D  / BN, Lp / BM, B), blk>>>(S1, q, prec, Lp, D, Lq, 1.0f);

    // ---- energy = softmax(q . v^T * scale) . v ----
    sgemm_kernel<true ><<<dim3(Lv / BN, Lq / BM, B), blk>>>(q, v, S2, Lq, Lv, D, scale);
    softmax_rows_kernel<2><<<B * Lq, blk>>>(S2, Lv);
    sgemm_kernel<false><<<dim3(D  / BN, Lq / BM, B), blk>>>(S2, v, energy, Lq, D, Lv, 1.0f);

    // ---- weightedContext = energy . v ----
    sgemm_kernel<false><<<dim3(D  / BN, Lq / BM, B), blk>>>(energy, v, wc, Lq, D, Lv, 1.0f);
}

// round 3
// speedup vs baseline: 2.8663x; 2.8663x over previous
#include <cuda_runtime.h>
#include <cstdint>
#include <math.h>

// ---------------------------------------------------------------------------
// Shapes (fixed): B=32, Lp=1024, Lq=1024, Lv=512, D=512, all fp32 row-major.
// Outputs: weightedContext [B,Lq,D], energy [B,Lq,D], precompute [B,Lp,D].
//
// tcgen05 is NOT available (harness compiles for plain sm_103 — no 'a'
// features). Tensor path = mma.sync.m16n8k8 TF32 (sm_80+ baseline PTX).
// All 5 GEMMs run NT (A[M,K] * B[N,K]^T); q and v pre-transposed once.
// ---------------------------------------------------------------------------

namespace {

// ======================= Scratch (device globals) ==========================
__device__ float g_S1[32u * 1024u * 1024u];  // pre.q^T scores   (134 MB)
__device__ float g_S2[32u * 1024u * 512u];   // q.v^T scores     ( 67 MB)
__device__ float g_qT[32u * 512u * 1024u];   // q transposed     ( 64 MB)
__device__ float g_vT[32u * 512u * 512u];    // v transposed     ( 32 MB)

// ======================= small PTX helpers =================================
__device__ __forceinline__ uint32_t smem_u32(const void* p) {
    uint32_t a;
    asm("{ .reg .u64 t; cvta.to.shared.u64 t, %1; cvt.u32.u64 %0, t; }"
        : "=r"(a) : "l"(p));
    return a;
}
__device__ __forceinline__ void cp_async16(uint32_t dst, const void* src) {
    asm volatile("cp.async.cg.shared.global [%0], [%1], 16;"
                 :: "r"(dst), "l"(src) : "memory");
}
#define CP_COMMIT() asm volatile("cp.async.commit_group;" ::: "memory")
#define CP_WAIT(n)  asm volatile("cp.async.wait_group %0;" :: "n"(n) : "memory")

__device__ __forceinline__ uint32_t f2tf32(float x) {
    uint32_t r;
    asm("cvt.rna.tf32.f32 %0, %1;" : "=r"(r) : "f"(x));
    return r;
}
__device__ __forceinline__ void mma_tf32(float* c, const uint32_t* a,
                                         const uint32_t* b) {
    asm volatile(
        "mma.sync.aligned.m16n8k8.row.col.f32.tf32.tf32.f32 "
        "{%0,%1,%2,%3}, {%4,%5,%6,%7}, {%8,%9}, {%0,%1,%2,%3};"
        : "+f"(c[0]), "+f"(c[1]), "+f"(c[2]), "+f"(c[3])
        : "r"(a[0]), "r"(a[1]), "r"(a[2]), "r"(a[3]), "r"(b[0]), "r"(b[1]));
}

// ======================= TF32 mma.sync NT GEMM =============================
// C[M,N] = alpha * A[M,K] * B[N,K]^T  (row-major, batched via blockIdx.z)
// CTA tile 128x128, BK=16, 8 warps (warp tile 64x32), 2-stage cp.async.
constexpr int BM = 128, BN = 128, BK = 16;
constexpr int BKP = BK + 4;                 // pad -> conflict-free frag loads

__global__ __launch_bounds__(256, 2)
void mma_nt_kernel(const float* __restrict__ A, const float* __restrict__ Bm,
                   float* __restrict__ C, int M, int N, int K, float alpha)
{
    __shared__ float As[2][BM * BKP];       // 2 x 10 KB
    __shared__ float Bs[2][BN * BKP];       // 2 x 10 KB

    const int tid = threadIdx.x;
    const int wid = tid >> 5;
    const int lane = tid & 31;
    const int wm = wid & 1;                 // 2 warps along M
    const int wn = wid >> 1;                // 4 warps along N
    const int g = lane >> 2;                // group id 0..7
    const int q = lane & 3;                 // thread-in-group 0..3

    const int rowA0 = blockIdx.y * BM;
    const int colB0 = blockIdx.x * BN;

    A  += (size_t)blockIdx.z * M * K + (size_t)rowA0 * K;
    Bm += (size_t)blockIdx.z * N * K + (size_t)colB0 * K;
    C  += (size_t)blockIdx.z * M * N;

    const uint32_t sA0 = smem_u32(&As[0][0]);
    const uint32_t sB0 = smem_u32(&Bs[0][0]);

    float acc[4][4][4];
#pragma unroll
    for (int f = 0; f < 4; f++)
#pragma unroll
        for (int n = 0; n < 4; n++)
#pragma unroll
            for (int i = 0; i < 4; i++) acc[f][n][i] = 0.0f;

    const int KT = K / BK;

    auto load_tile = [&](int kt, int s) {
        const float* gA = A + (size_t)kt * BK;
        const float* gB = Bm + (size_t)kt * BK;
        const uint32_t dA = sA0 + (uint32_t)s * (BM * BKP * 4);
        const uint32_t dB = sB0 + (uint32_t)s * (BN * BKP * 4);
#pragma unroll
        for (int i = 0; i < 2; i++) {       // A: 512 x 16B chunks
            const int ch = tid + i * 256;
            const int r = ch >> 2, c = ch & 3;
            cp_async16(dA + (uint32_t)(r * BKP + c * 4) * 4,
                       gA + (size_t)r * K + c * 4);
        }
#pragma unroll
        for (int i = 0; i < 2; i++) {       // B: 512 x 16B chunks
            const int ch = tid + i * 256;
            const int r = ch >> 2, c = ch & 3;
            cp_async16(dB + (uint32_t)(r * BKP + c * 4) * 4,
                       gB + (size_t)r * K + c * 4);
        }
    };

    load_tile(0, 0);
    CP_COMMIT();

    for (int kt = 0; kt < KT; kt++) {
        const int s = kt & 1;
        if (kt + 1 < KT) {
            load_tile(kt + 1, (kt + 1) & 1);
            CP_COMMIT();
            CP_WAIT(1);
        } else {
            CP_WAIT(0);
        }
        __syncthreads();

        const float* as = &As[s][0];
        const float* bs = &Bs[s][0];
#pragma unroll
        for (int ks = 0; ks < 2; ks++) {
            const int k0 = ks * 8;
            uint32_t a[4][4], b[4][2];
#pragma unroll
            for (int f = 0; f < 4; f++) {
                const int r0 = wm * 64 + f * 16 + g;
                a[f][0] = f2tf32(as[r0 * BKP + k0 + q]);
                a[f][1] = f2tf32(as[(r0 + 8) * BKP + k0 + q]);
                a[f][2] = f2tf32(as[r0 * BKP + k0 + q + 4]);
                a[f][3] = f2tf32(as[(r0 + 8) * BKP + k0 + q + 4]);
            }
#pragma unroll
            for (int n = 0; n < 4; n++) {
                const int c0 = wn * 32 + n * 8 + g;
                b[n][0] = f2tf32(bs[c0 * BKP + k0 + q]);
                b[n][1] = f2tf32(bs[c0 * BKP + k0 + q + 4]);
            }
#pragma unroll
            for (int f = 0; f < 4; f++)
#pragma unroll
                for (int n = 0; n < 4; n++) mma_tf32(acc[f][n], a[f], b[n]);
        }
        __syncthreads();
    }

    // epilogue
#pragma unroll
    for (int f = 0; f < 4; f++) {
        const int row = rowA0 + wm * 64 + f * 16 + g;
#pragma unroll
        for (int n = 0; n < 4; n++) {
            const int col = colB0 + wn * 32 + n * 8 + 2 * q;
            float2 v0, v1;
            v0.x = acc[f][n][0] * alpha;
            v0.y = acc[f][n][1] * alpha;
            v1.x = acc[f][n][2] * alpha;
            v1.y = acc[f][n][3] * alpha;
            *reinterpret_cast<float2*>(C + (size_t)row * N + col) = v0;
            *reinterpret_cast<float2*>(C + (size_t)(row + 8) * N + col) = v1;
        }
    }
}

// ======================= transpose =========================================
__global__ __launch_bounds__(256)
void transpose_kernel(const float* __restrict__ in, float* __restrict__ out,
                      int R, int Cc)
{
    __shared__ float t[32][33];
    const int b = blockIdx.z;
    in  += (size_t)b * R * Cc;
    out += (size_t)b * R * Cc;
    const int c0 = blockIdx.x * 32, r0 = blockIdx.y * 32;
#pragma unroll
    for (int i = threadIdx.y; i < 32; i += 8)
        t[i][threadIdx.x] = in[(size_t)(r0 + i) * Cc + c0 + threadIdx.x];
    __syncthreads();
#pragma unroll
    for (int i = threadIdx.y; i < 32; i += 8)
        out[(size_t)(c0 + i) * R + r0 + threadIdx.x] = t[threadIdx.x][i];
}

// ======================= row softmax =======================================
template <int ELEMS>
__global__ __launch_bounds__(256)
void softmax_rows_kernel(float* __restrict__ S, int W)
{
    float* p = S + (size_t)blockIdx.x * W;
    const int tid = threadIdx.x;

    float vals[ELEMS];
    float m = -3.4e38f;
#pragma unroll
    for (int i = 0; i < ELEMS; i++) {
        vals[i] = p[tid + (i << 8)];
        m = fmaxf(m, vals[i]);
    }

    __shared__ float red[8];
    __shared__ float bc;

#pragma unroll
    for (int o = 16; o > 0; o >>= 1)
        m = fmaxf(m, __shfl_xor_sync(0xffffffffu, m, o));
    if ((tid & 31) == 0) red[tid >> 5] = m;
    __syncthreads();
    if (tid == 0) {
        float t = red[0];
#pragma unroll
        for (int i = 1; i < 8; i++) t = fmaxf(t, red[i]);
        bc = t;
    }
    __syncthreads();
    m = bc;

    float s = 0.0f;
#pragma unroll
    for (int i = 0; i < ELEMS; i++) {
        vals[i] = expf(vals[i] - m);
        s += vals[i];
    }
    __syncthreads();

#pragma unroll
    for (int o = 16; o > 0; o >>= 1)
        s += __shfl_xor_sync(0xffffffffu, s, o);
    if ((tid & 31) == 0) red[tid >> 5] = s;
    __syncthreads();
    if (tid == 0) {
        float t = red[0];
#pragma unroll
        for (int i = 1; i < 8; i++) t += red[i];
        bc = 1.0f / t;
    }
    __syncthreads();
    const float inv = bc;

#pragma unroll
    for (int i = 0; i < ELEMS; i++)
        p[tid + (i << 8)] = vals[i] * inv;
}

}  // namespace

// ===========================================================================
extern "C" void kernel_launch(void* const* d_in, const int* in_sizes, int n_in,
                              void* d_out, int out_size)
{
    const float* pre = (const float*)d_in[0];  // [32,1024,512]
    const float* q   = (const float*)d_in[1];  // [32,1024,512]
    const float* v   = (const float*)d_in[2];  // [32, 512,512]
    float* out = (float*)d_out;

    const int B = 32, Lp = 1024, Lq = 1024, Lv = 512, D = 512;
    const float scale = 0.04419417382415922f;  // 1/sqrt(512)

    float* wc     = out;                           // [B,Lq,D]
    float* energy = out + (size_t)B * Lq * D;      // [B,Lq,D]
    float* prec   = out + 2 * (size_t)B * Lq * D;  // [B,Lp,D]

    float *S1, *S2, *qT, *vT;
    cudaGetSymbolAddress((void**)&S1, g_S1);
    cudaGetSymbolAddress((void**)&S2, g_S2);
    cudaGetSymbolAddress((void**)&qT, g_qT);
    cudaGetSymbolAddress((void**)&vT, g_vT);

    // transposes: qT[b] = q[b]^T (D x Lq), vT[b] = v[b]^T (D x Lv)
    transpose_kernel<<<dim3(D / 32, Lq / 32, B), dim3(32, 8)>>>(q, qT, Lq, D);
    transpose_kernel<<<dim3(D / 32, Lv / 32, B), dim3(32, 8)>>>(v, vT, Lv, D);

    const dim3 blk(256);

    // precompute stream: S1 = softmax(pre.q^T * scale); prec = S1.q
    mma_nt_kernel<<<dim3(Lq / BN, Lp / BM, B), blk>>>(pre, q, S1, Lp, Lq, D, scale);
    softmax_rows_kernel<4><<<B * Lp, 256>>>(S1, Lq);
    mma_nt_kernel<<<dim3(D / BN, Lp / BM, B), blk>>>(S1, qT, prec, Lp, D, Lq, 1.0f);

    // energy stream: S2 = softmax(q.v^T * scale); energy = S2.v
    mma_nt_kernel<<<dim3(Lv / BN, Lq / BM, B), blk>>>(q, v, S2, Lq, Lv, D, scale);
    softmax_rows_kernel<2><<<B * Lq, 256>>>(S2, Lv);
    mma_nt_kernel<<<dim3(D / BN, Lq / BM, B), blk>>>(S2, vT, energy, Lq, D, Lv, 1.0f);

    // weightedContext = energy . v
    mma_nt_kernel<<<dim3(D / BN, Lq / BM, B), blk>>>(energy, vT, wc, Lq, D, Lv, 1.0f);
}